// round 16
// baseline (speedup 1.0000x reference)
#include <cuda_runtime.h>
#include <cuda_bf16.h>
#include <cstdint>

// ============================================================================
// SigmoidAttention: B=4, S=4096, D=1024
//   Q = X@Wq + bq ; K = X@Wk + bk ; V = X@Wv + bv
//   w = sigmoid(Q K^T / sqrt(D)) ;  O = w @ V
// Strategy: bf16x3 split-GEMM (hi/lo decomposition, fp32 accumulate) on
// mma.sync.m16n8k16 tensor cores. One templated NT-GEMM serves all stages.
// ============================================================================

#define BSZ  4
#define SSZ  4096
#define DSZ  1024
#define MTOT (BSZ * SSZ)   // 16384

// ---------------- scratch (device globals; no allocation allowed) ----------
static __device__ float g_Q [(size_t)MTOT * DSZ];        // 64 MB
static __device__ float g_K [(size_t)MTOT * DSZ];        // 64 MB
static __device__ float g_Vt[(size_t)DSZ  * MTOT];       // 64 MB, V transposed [D][B*S]
static __device__ float g_Wt[3u * 1024u * 1024u];        // 12 MB, W transposed [n][k] x3
static __device__ float g_w [(size_t)BSZ * SSZ * SSZ];   // 256 MB, sigmoid weights

// ---------------- tiling constants ----------------
constexpr int BM = 128;
constexpr int BN = 128;
constexpr int BK = 32;
constexpr int SM_STRIDE = 40;                       // padded bf16 row -> conflict-free ldmatrix
constexpr int OP_ELEMS  = 2 * 2 * BM * SM_STRIDE;   // [buf][hi/lo][128][40] per operand
constexpr int SMEM_BYTES = 2 * OP_ELEMS * (int)sizeof(__nv_bfloat16);  // 81920

// ---------------- small helpers ----------------
__device__ __forceinline__ uint32_t pack_bf2(__nv_bfloat16 a, __nv_bfloat16 b) {
    return (uint32_t)__bfloat16_as_ushort(a) | ((uint32_t)__bfloat16_as_ushort(b) << 16);
}

__device__ __forceinline__ void ldsm_x4(uint32_t r[4], const __nv_bfloat16* p) {
    uint32_t addr = (uint32_t)__cvta_generic_to_shared(p);
    asm volatile("ldmatrix.sync.aligned.m8n8.x4.shared.b16 {%0,%1,%2,%3}, [%4];\n"
                 : "=r"(r[0]), "=r"(r[1]), "=r"(r[2]), "=r"(r[3])
                 : "r"(addr));
}

__device__ __forceinline__ void mma_bf16(float c[4], const uint32_t a[4],
                                         uint32_t b0, uint32_t b1) {
    asm volatile(
        "mma.sync.aligned.m16n8k16.row.col.f32.bf16.bf16.f32 "
        "{%0,%1,%2,%3}, {%4,%5,%6,%7}, {%8,%9}, {%0,%1,%2,%3};\n"
        : "+f"(c[0]), "+f"(c[1]), "+f"(c[2]), "+f"(c[3])
        : "r"(a[0]), "r"(a[1]), "r"(a[2]), "r"(a[3]), "r"(b0), "r"(b1));
}

// Split one float4 into hi/lo bf16 quads and store 8B each.
__device__ __forceinline__ void split_store4(__nv_bfloat16* hi_p, __nv_bfloat16* lo_p,
                                             float4 v) {
    __nv_bfloat16 h0 = __float2bfloat16(v.x);
    __nv_bfloat16 h1 = __float2bfloat16(v.y);
    __nv_bfloat16 h2 = __float2bfloat16(v.z);
    __nv_bfloat16 h3 = __float2bfloat16(v.w);
    __nv_bfloat16 l0 = __float2bfloat16(v.x - __bfloat162float(h0));
    __nv_bfloat16 l1 = __float2bfloat16(v.y - __bfloat162float(h1));
    __nv_bfloat16 l2 = __float2bfloat16(v.z - __bfloat162float(h2));
    __nv_bfloat16 l3 = __float2bfloat16(v.w - __bfloat162float(h3));
    *reinterpret_cast<uint2*>(hi_p) = make_uint2(pack_bf2(h0, h1), pack_bf2(h2, h3));
    *reinterpret_cast<uint2*>(lo_p) = make_uint2(pack_bf2(l0, l1), pack_bf2(l2, l3));
}

// ---------------- W transpose: Wt[n][k] = W[k][n], 1024x1024 ----------------
__global__ void transpose1024(const float* __restrict__ W, float* __restrict__ Wt) {
    __shared__ float tile[32][33];
    const int bx = blockIdx.x * 32, by = blockIdx.y * 32;
    const int tx = threadIdx.x, ty = threadIdx.y;   // blockDim (32,8)
#pragma unroll
    for (int j = 0; j < 32; j += 8)
        tile[ty + j][tx] = W[(size_t)(by + ty + j) * 1024 + bx + tx];
    __syncthreads();
#pragma unroll
    for (int j = 0; j < 32; j += 8)
        Wt[(size_t)(bx + ty + j) * 1024 + by + tx] = tile[tx][ty + j];
}

// ============================================================================
// Generic NT split-bf16 GEMM:  C[m][n] = epilogue( sum_k A[m][k] * Bop[n][k] )
// MODE 0: +bias, store C[m*ldc+n]          (Q / K projection)
// MODE 1: +bias, store transposed C[n*ldc+m] (V projection -> g_Vt)
// MODE 2: sigmoid(acc*scale), store C[m*ldc+n] (scores -> weights)
// MODE 3: plain store C[m*ldc+n]           (weights @ V -> output)
// Requires: M%128==0, N%128==0, K%32==0 (true for all stages).
// ============================================================================
template <int MODE>
__global__ void __launch_bounds__(256, 1)
gemm_split_kernel(const float* __restrict__ A, long long Az, int lda,
                  const float* __restrict__ Bm, long long Bz, int ldb,
                  const float* __restrict__ bias,
                  float* __restrict__ C, long long Cz, int ldc,
                  int K, float scale)
{
    extern __shared__ __nv_bfloat16 smem[];
    __nv_bfloat16* sA = smem;
    __nv_bfloat16* sB = smem + OP_ELEMS;

    const int tid  = threadIdx.x;
    const int lane = tid & 31;
    const int warp = tid >> 5;
    const int wm = (warp >> 2) * 64;     // 2 warp-rows
    const int wn = (warp & 3) * 32;      // 4 warp-cols

    const int m0 = blockIdx.y * BM;
    const int n0 = blockIdx.x * BN;
    const long long zA = Az * blockIdx.z;
    const long long zB = Bz * blockIdx.z;
    const long long zC = Cz * blockIdx.z;

    // global->smem staging map: 256 threads, each loads 4 float4 per operand
    const int ldRow = tid >> 3;          // 0..31
    const int ldCol = (tid & 7) * 4;     // 0,4,...,28

    const float* Aptr = A + zA + (long long)(m0 + ldRow) * lda + ldCol;
    const float* Bptr = Bm + zB + (long long)(n0 + ldRow) * ldb + ldCol;

    float acc[4][4][4];
#pragma unroll
    for (int i = 0; i < 4; ++i)
#pragma unroll
        for (int j = 0; j < 4; ++j)
#pragma unroll
            for (int r = 0; r < 4; ++r) acc[i][j][r] = 0.f;

    float4 ra[4], rb[4];

    // ---- prologue: load + stage chunk 0 into buf 0 ----
#pragma unroll
    for (int r = 0; r < 4; ++r) {
        ra[r] = *reinterpret_cast<const float4*>(Aptr + (long long)(r * 32) * lda);
        rb[r] = *reinterpret_cast<const float4*>(Bptr + (long long)(r * 32) * ldb);
    }
#pragma unroll
    for (int r = 0; r < 4; ++r) {
        const int row = ldRow + r * 32;
        split_store4(sA + ((0 * 2 + 0) * BM + row) * SM_STRIDE + ldCol,
                     sA + ((0 * 2 + 1) * BM + row) * SM_STRIDE + ldCol, ra[r]);
        split_store4(sB + ((0 * 2 + 0) * BM + row) * SM_STRIDE + ldCol,
                     sB + ((0 * 2 + 1) * BM + row) * SM_STRIDE + ldCol, rb[r]);
    }
    __syncthreads();

    const int nChunks = K / BK;
    for (int kc = 0; kc < nChunks; ++kc) {
        const int buf = kc & 1;
        const bool hasNext = (kc + 1 < nChunks);

        if (hasNext) {
            const long long kabs = (long long)(kc + 1) * BK;
#pragma unroll
            for (int r = 0; r < 4; ++r) {
                ra[r] = *reinterpret_cast<const float4*>(Aptr + (long long)(r * 32) * lda + kabs);
                rb[r] = *reinterpret_cast<const float4*>(Bptr + (long long)(r * 32) * ldb + kabs);
            }
        }

        // ---- compute on buf ----
#pragma unroll
        for (int ks = 0; ks < BK; ks += 16) {
            uint32_t ah[4][4], alo[4][4];
            const int arow = wm + (lane & 15);
            const int acol = ks + (lane >> 4) * 8;
#pragma unroll
            for (int i = 0; i < 4; ++i) {
                ldsm_x4(ah[i],  sA + ((buf * 2 + 0) * BM + arow + i * 16) * SM_STRIDE + acol);
                ldsm_x4(alo[i], sA + ((buf * 2 + 1) * BM + arow + i * 16) * SM_STRIDE + acol);
            }
            uint32_t bh[2][4], blo[2][4];
            const int brow = wn + (lane & 7) + ((lane >> 4) << 3);
            const int bcol = ks + ((lane >> 3) & 1) * 8;
#pragma unroll
            for (int j2 = 0; j2 < 2; ++j2) {
                ldsm_x4(bh[j2],  sB + ((buf * 2 + 0) * BM + brow + j2 * 16) * SM_STRIDE + bcol);
                ldsm_x4(blo[j2], sB + ((buf * 2 + 1) * BM + brow + j2 * 16) * SM_STRIDE + bcol);
            }
            // hi*hi
#pragma unroll
            for (int i = 0; i < 4; ++i)
#pragma unroll
                for (int j = 0; j < 4; ++j)
                    mma_bf16(acc[i][j], ah[i], bh[j >> 1][(j & 1) * 2], bh[j >> 1][(j & 1) * 2 + 1]);
            // hi*lo
#pragma unroll
            for (int i = 0; i < 4; ++i)
#pragma unroll
                for (int j = 0; j < 4; ++j)
                    mma_bf16(acc[i][j], ah[i], blo[j >> 1][(j & 1) * 2], blo[j >> 1][(j & 1) * 2 + 1]);
            // lo*hi
#pragma unroll
            for (int i = 0; i < 4; ++i)
#pragma unroll
                for (int j = 0; j < 4; ++j)
                    mma_bf16(acc[i][j], alo[i], bh[j >> 1][(j & 1) * 2], bh[j >> 1][(j & 1) * 2 + 1]);
        }

        if (hasNext) {
            const int buf2 = buf ^ 1;
#pragma unroll
            for (int r = 0; r < 4; ++r) {
                const int row = ldRow + r * 32;
                split_store4(sA + ((buf2 * 2 + 0) * BM + row) * SM_STRIDE + ldCol,
                             sA + ((buf2 * 2 + 1) * BM + row) * SM_STRIDE + ldCol, ra[r]);
                split_store4(sB + ((buf2 * 2 + 0) * BM + row) * SM_STRIDE + ldCol,
                             sB + ((buf2 * 2 + 1) * BM + row) * SM_STRIDE + ldCol, rb[r]);
            }
        }
        __syncthreads();
    }

    // ---- epilogue ----
#pragma unroll
    for (int i = 0; i < 4; ++i) {
        const int m = m0 + wm + i * 16 + (lane >> 2);
#pragma unroll
        for (int j = 0; j < 4; ++j) {
            const int n = n0 + wn + j * 8 + (lane & 3) * 2;
            float c0 = acc[i][j][0], c1 = acc[i][j][1];
            float c2 = acc[i][j][2], c3 = acc[i][j][3];

            if (MODE == 0 || MODE == 1) {
                const float b0 = bias[n], b1 = bias[n + 1];
                c0 += b0; c1 += b1; c2 += b0; c3 += b1;
            }
            if (MODE == 2) {
                c0 = 1.f / (1.f + __expf(-c0 * scale));
                c1 = 1.f / (1.f + __expf(-c1 * scale));
                c2 = 1.f / (1.f + __expf(-c2 * scale));
                c3 = 1.f / (1.f + __expf(-c3 * scale));
            }

            if (MODE == 1) {
                float* Cb = C + zC;
                Cb[(long long)n * ldc + m]           = c0;
                Cb[(long long)(n + 1) * ldc + m]     = c1;
                Cb[(long long)n * ldc + m + 8]       = c2;
                Cb[(long long)(n + 1) * ldc + m + 8] = c3;
            } else {
                float* Crow = C + zC + (long long)m * ldc + n;
                *reinterpret_cast<float2*>(Crow)                      = make_float2(c0, c1);
                *reinterpret_cast<float2*>(Crow + (long long)8 * ldc) = make_float2(c2, c3);
            }
        }
    }
}

// ============================================================================
// Host launcher (graph-capturable: kernel launches only)
// ============================================================================
extern "C" void kernel_launch(void* const* d_in, const int* in_sizes, int n_in,
                              void* d_out, int out_size)
{
    (void)in_sizes; (void)n_in; (void)out_size;
    const float* X  = (const float*)d_in[0];
    const float* Wq = (const float*)d_in[1];
    const float* bq = (const float*)d_in[2];
    const float* Wk = (const float*)d_in[3];
    const float* bk = (const float*)d_in[4];
    const float* Wv = (const float*)d_in[5];
    const float* bv = (const float*)d_in[6];
    float* out = (float*)d_out;

    float *Q, *Kbuf, *Vt, *Wt, *wbuf;
    cudaGetSymbolAddress((void**)&Q,    g_Q);
    cudaGetSymbolAddress((void**)&Kbuf, g_K);
    cudaGetSymbolAddress((void**)&Vt,   g_Vt);
    cudaGetSymbolAddress((void**)&Wt,   g_Wt);
    cudaGetSymbolAddress((void**)&wbuf, g_w);

    cudaFuncSetAttribute(gemm_split_kernel<0>, cudaFuncAttributeMaxDynamicSharedMemorySize, SMEM_BYTES);
    cudaFuncSetAttribute(gemm_split_kernel<1>, cudaFuncAttributeMaxDynamicSharedMemorySize, SMEM_BYTES);
    cudaFuncSetAttribute(gemm_split_kernel<2>, cudaFuncAttributeMaxDynamicSharedMemorySize, SMEM_BYTES);
    cudaFuncSetAttribute(gemm_split_kernel<3>, cudaFuncAttributeMaxDynamicSharedMemorySize, SMEM_BYTES);

    // 0) transpose the three weight matrices: Wt[n][k] = W[k][n]
    dim3 ttb(32, 8);
    transpose1024<<<dim3(32, 32), ttb>>>(Wq, Wt);
    transpose1024<<<dim3(32, 32), ttb>>>(Wk, Wt + 1024 * 1024);
    transpose1024<<<dim3(32, 32), ttb>>>(Wv, Wt + 2 * 1024 * 1024);

    // 1) projections: [16384,1024] x [1024,1024]
    gemm_split_kernel<0><<<dim3(8, 128, 1), 256, SMEM_BYTES>>>(
        X, 0, DSZ, Wt, 0, DSZ, bq, Q, 0, DSZ, DSZ, 0.f);
    gemm_split_kernel<0><<<dim3(8, 128, 1), 256, SMEM_BYTES>>>(
        X, 0, DSZ, Wt + 1024 * 1024, 0, DSZ, bk, Kbuf, 0, DSZ, DSZ, 0.f);
    // V stored transposed: Vt[d][b*S+s]
    gemm_split_kernel<1><<<dim3(8, 128, 1), 256, SMEM_BYTES>>>(
        X, 0, DSZ, Wt + 2 * 1024 * 1024, 0, DSZ, bv, Vt, 0, MTOT, DSZ, 0.f);

    // 2) scores + sigmoid: per batch [4096,1024] x [4096,1024]^T -> w[4096,4096]
    gemm_split_kernel<2><<<dim3(32, 32, BSZ), 256, SMEM_BYTES>>>(
        Q,    (long long)SSZ * DSZ, DSZ,
        Kbuf, (long long)SSZ * DSZ, DSZ,
        nullptr,
        wbuf, (long long)SSZ * SSZ, SSZ,
        DSZ, 0.03125f /* 1/sqrt(1024) */);

    // 3) output: per batch w[4096,4096] x Vt[1024, b*S + k] -> out[4096,1024]
    gemm_split_kernel<3><<<dim3(8, 32, BSZ), 256, SMEM_BYTES>>>(
        wbuf, (long long)SSZ * SSZ, SSZ,
        Vt,   (long long)SSZ,       MTOT,
        nullptr,
        out,  (long long)SSZ * DSZ, DSZ,
        SSZ, 0.f);
}